// round 1
// baseline (speedup 1.0000x reference)
#include <cuda_runtime.h>
#include <cstdint>

// Problem constants
#define ROWS 4096
#define COLS 11008
#define RANK 32
#define CB_HALF (256 * 8)        // floats per codebook
#define CODES_PER_CB 2818048     // (ROWS*COLS/8)/2
#define I_SPLIT 2048             // i >= 2048 -> codebook 1 (22544384/11008)

#define TI 128
#define TJ 128
#define THREADS 256

// Packed fp32x2 FMA (Blackwell FFMA2) — only reachable via PTX.
__device__ __forceinline__ float2 ffma2(float2 a, float2 b, float2 c) {
    unsigned long long A = *reinterpret_cast<unsigned long long*>(&a);
    unsigned long long B = *reinterpret_cast<unsigned long long*>(&b);
    unsigned long long C = *reinterpret_cast<unsigned long long*>(&c);
    unsigned long long D;
    asm("fma.rn.f32x2 %0, %1, %2, %3;" : "=l"(D) : "l"(A), "l"(B), "l"(C));
    return *reinterpret_cast<float2*>(&D);
}

__global__ __launch_bounds__(THREADS, 2)
void qw_dequant_lr_kernel(const float* __restrict__ codebooks,  // (2,256,8)
                          const int*   __restrict__ codes,      // (2, 2818048) flat
                          const float* __restrict__ scales,     // (11008,)
                          const float* __restrict__ L,          // (4096,32)
                          const float* __restrict__ R,          // (32,11008)
                          float*       __restrict__ out)        // (4096,11008)
{
    __shared__ float Ls[TI][RANK + 1];   // +1 pad: conflict-free i-major writes/reads
    __shared__ float Rs[RANK][TJ];       // r-major, j contiguous (float4-aligned reads)

    const int tid = threadIdx.x;
    const int tx  = tid & 15;            // j-oct index   (16 octs = 128 cols)
    const int ty  = tid >> 4;            // i-strip index (16 strips of 8 rows)
    const int i0  = blockIdx.y * TI;
    const int j0  = blockIdx.x * TJ;

    // ---- stage L tile (coalesced gmem, conflict-free smem) ----
    #pragma unroll
    for (int t = tid; t < TI * RANK; t += THREADS) {
        int il = t >> 5, r = t & 31;
        Ls[il][r] = L[(i0 + il) * RANK + r];
    }
    // ---- stage R tile ----
    #pragma unroll
    for (int t = tid; t < RANK * TJ; t += THREADS) {
        int r = t >> 7, jl = t & 127;
        Rs[r][jl] = R[r * COLS + j0 + jl];
    }
    __syncthreads();

    // ---- LR micro-tile: 8i x 8j per thread, packed f32x2 accumulators ----
    float2 acc[8][4];
    #pragma unroll
    for (int ii = 0; ii < 8; ii++)
        #pragma unroll
        for (int jj = 0; jj < 4; jj++)
            acc[ii][jj] = make_float2(0.f, 0.f);

    const int ib = ty * 8;
    const int jb = tx * 8;

    #pragma unroll
    for (int r = 0; r < RANK; r++) {
        float4 ra = *reinterpret_cast<const float4*>(&Rs[r][jb]);
        float4 rb = *reinterpret_cast<const float4*>(&Rs[r][jb + 4]);
        float2 rv[4];
        rv[0] = make_float2(ra.x, ra.y);
        rv[1] = make_float2(ra.z, ra.w);
        rv[2] = make_float2(rb.x, rb.y);
        rv[3] = make_float2(rb.z, rb.w);
        #pragma unroll
        for (int ii = 0; ii < 8; ii++) {
            float  lv = Ls[ib + ii][r];
            float2 l2 = make_float2(lv, lv);
            #pragma unroll
            for (int jj = 0; jj < 4; jj++)
                acc[ii][jj] = ffma2(l2, rv[jj], acc[ii][jj]);
        }
    }

    // ---- fused dequant epilogue: one code group (8 elems) per (ii) row ----
    #pragma unroll
    for (int ii = 0; ii < 8; ii++) {
        const int i = i0 + ib + ii;
        const unsigned int f = (unsigned int)i * COLS + (unsigned int)(j0 + jb);
        const unsigned int g = f >> 3;           // code index (== flat codes index)
        const int code = __ldg(&codes[g]);
        const float* cb = codebooks + ((i >= I_SPLIT) ? CB_HALF : 0) + code * 8;
        const float4 c0 = __ldg(reinterpret_cast<const float4*>(cb));
        const float4 c1 = __ldg(reinterpret_cast<const float4*>(cb) + 1);
        const float  s  = __ldg(&scales[f >> 12]);   // constant within the group

        float4 o0, o1;
        o0.x = fmaf(c0.x, s, acc[ii][0].x);
        o0.y = fmaf(c0.y, s, acc[ii][0].y);
        o0.z = fmaf(c0.z, s, acc[ii][1].x);
        o0.w = fmaf(c0.w, s, acc[ii][1].y);
        o1.x = fmaf(c1.x, s, acc[ii][2].x);
        o1.y = fmaf(c1.y, s, acc[ii][2].y);
        o1.z = fmaf(c1.z, s, acc[ii][3].x);
        o1.w = fmaf(c1.w, s, acc[ii][3].y);

        *reinterpret_cast<float4*>(&out[f])     = o0;
        *reinterpret_cast<float4*>(&out[f + 4]) = o1;
    }
}

extern "C" void kernel_launch(void* const* d_in, const int* in_sizes, int n_in,
                              void* d_out, int out_size) {
    const float* codebooks = (const float*)d_in[0];
    const int*   codes     = (const int*)  d_in[1];
    const float* scales    = (const float*)d_in[2];
    const float* L         = (const float*)d_in[3];
    const float* R         = (const float*)d_in[4];
    float*       out       = (float*)d_out;

    dim3 grid(COLS / TJ, ROWS / TI);   // (86, 32)
    qw_dequant_lr_kernel<<<grid, THREADS>>>(codebooks, codes, scales, L, R, out);
}

// round 3
// speedup vs baseline: 1.3901x; 1.3901x over previous
#include <cuda_runtime.h>
#include <cuda_bf16.h>
#include <cstdint>

#define ROWS 4096
#define COLS 11008
#define RANK 32
#define CB_HALF 2048          // floats per codebook (256*8)
#define I_SPLIT 2048          // i >= 2048 -> codebook 1

#define TI 128
#define TJ 128
#define THREADS 256

// smem layout (dynamic): conflict-free strides
#define AS_STRIDE 40          // bf16 per row (A: 128 x 32)
#define BS_STRIDE 40          // bf16 per row (B: 128n x 32k)
#define CS_STRIDE 136         // bf16 per row (C: 128 x 128), 272B = 17*16B
#define AS_BYTES (TI * AS_STRIDE * 2)            // 10240
#define BS_BYTES (TJ * BS_STRIDE * 2)            // 10240
#define CS_BYTES (TI * CS_STRIDE * 2)            // 34816
#define CB_BYTES (2 * CB_HALF * 4)               // 16384
#define SMEM_TOTAL (AS_BYTES + BS_BYTES + CS_BYTES + CB_BYTES)   // 71680

__global__ __launch_bounds__(THREADS, 2)
void qw_hmma_kernel(const float* __restrict__ codebooks,  // (2,256,8)
                    const int*   __restrict__ codes,      // flat
                    const float* __restrict__ scales,     // (11008,)
                    const float* __restrict__ L,          // (4096,32)
                    const float* __restrict__ R,          // (32,11008)
                    float*       __restrict__ out)        // (4096,11008)
{
    extern __shared__ char smem[];
    __nv_bfloat16* As  = reinterpret_cast<__nv_bfloat16*>(smem);
    __nv_bfloat16* Bs  = reinterpret_cast<__nv_bfloat16*>(smem + AS_BYTES);
    __nv_bfloat16* Cs  = reinterpret_cast<__nv_bfloat16*>(smem + AS_BYTES + BS_BYTES);
    float*         cbs = reinterpret_cast<float*>(smem + AS_BYTES + BS_BYTES + CS_BYTES);

    const int tid = threadIdx.x;
    const int wid = tid >> 5;
    const int lid = tid & 31;
    const int i0  = blockIdx.y * TI;
    const int j0  = blockIdx.x * TJ;

    // ---- stage codebooks (16KB) to smem, float4 ----
    {
        const float4* src = reinterpret_cast<const float4*>(codebooks);
        float4*       dst = reinterpret_cast<float4*>(cbs);
        #pragma unroll
        for (int t = tid; t < (2 * CB_HALF) / 4; t += THREADS)
            dst[t] = src[t];
    }
    // ---- stage A = L tile [128 x 32] bf16 (coalesced reads) ----
    #pragma unroll
    for (int idx = tid; idx < TI * RANK; idx += THREADS) {
        int row = idx >> 5, k = idx & 31;
        As[row * AS_STRIDE + k] = __float2bfloat16(L[(i0 + row) * RANK + k]);
    }
    // ---- stage B = R^T tile [128n x 32k] bf16 (coalesced reads in n) ----
    #pragma unroll
    for (int idx = tid; idx < TJ * RANK; idx += THREADS) {
        int k = idx >> 7, n = idx & 127;
        Bs[n * BS_STRIDE + k] = __float2bfloat16(R[k * COLS + j0 + n]);
    }
    __syncthreads();

    // ---- HMMA mainloop: warp w computes rows [16w, 16w+16) x 128 cols ----
    // m16n8k16 bf16: 16 n-tiles, 2 k-steps.
    float acc[16][4];
    #pragma unroll
    for (int t = 0; t < 16; t++) {
        acc[t][0] = 0.f; acc[t][1] = 0.f; acc[t][2] = 0.f; acc[t][3] = 0.f;
    }
    {
        const int rA = wid * 16 + (lid >> 2);   // fragment row (and +8)
        const int q  = lid & 3;
        const int cB = lid >> 2;                // fragment col within n-tile
        #pragma unroll
        for (int ks = 0; ks < 2; ks++) {
            const int kb = ks * 16 + 2 * q;
            uint32_t a0 = *reinterpret_cast<const uint32_t*>(&As[rA * AS_STRIDE + kb]);
            uint32_t a1 = *reinterpret_cast<const uint32_t*>(&As[(rA + 8) * AS_STRIDE + kb]);
            uint32_t a2 = *reinterpret_cast<const uint32_t*>(&As[rA * AS_STRIDE + kb + 8]);
            uint32_t a3 = *reinterpret_cast<const uint32_t*>(&As[(rA + 8) * AS_STRIDE + kb + 8]);
            #pragma unroll
            for (int t = 0; t < 16; t++) {
                uint32_t b0 = *reinterpret_cast<const uint32_t*>(
                    &Bs[(t * 8 + cB) * BS_STRIDE + kb]);
                uint32_t b1 = *reinterpret_cast<const uint32_t*>(
                    &Bs[(t * 8 + cB) * BS_STRIDE + kb + 8]);
                asm volatile(
                    "mma.sync.aligned.m16n8k16.row.col.f32.bf16.bf16.f32 "
                    "{%0,%1,%2,%3}, {%4,%5,%6,%7}, {%8,%9}, {%0,%1,%2,%3};"
                    : "+f"(acc[t][0]), "+f"(acc[t][1]), "+f"(acc[t][2]), "+f"(acc[t][3])
                    : "r"(a0), "r"(a1), "r"(a2), "r"(a3), "r"(b0), "r"(b1));
            }
        }
    }

    // ---- write C to smem as bf16 (conflict-free STS.32) ----
    {
        const int r0  = wid * 16 + (lid >> 2);
        const int col = 2 * (lid & 3);
        #pragma unroll
        for (int t = 0; t < 16; t++) {
            uint32_t p0, p1;
            asm("cvt.rn.bf16x2.f32 %0, %1, %2;" : "=r"(p0) : "f"(acc[t][1]), "f"(acc[t][0]));
            asm("cvt.rn.bf16x2.f32 %0, %1, %2;" : "=r"(p1) : "f"(acc[t][3]), "f"(acc[t][2]));
            *reinterpret_cast<uint32_t*>(&Cs[r0 * CS_STRIDE + t * 8 + col])       = p0;
            *reinterpret_cast<uint32_t*>(&Cs[(r0 + 8) * CS_STRIDE + t * 8 + col]) = p1;
        }
    }
    __syncthreads();

    // ---- epilogue: thread (tx,ty) owns rows ty*8..+7, cols tx*8..+7 ----
    {
        const int tx = tid & 15;
        const int ty = tid >> 4;
        #pragma unroll
        for (int ii = 0; ii < 8; ii++) {
            const int r = ty * 8 + ii;
            const int i = i0 + r;
            const float* cb = cbs + ((i >= I_SPLIT) ? CB_HALF : 0);
            const unsigned f = (unsigned)i * COLS + (unsigned)(j0 + tx * 8);

            const int code = __ldg(&codes[f >> 3]);
            const float4 c0 = *reinterpret_cast<const float4*>(cb + code * 8);
            const float4 c1 = *reinterpret_cast<const float4*>(cb + code * 8 + 4);
            const float  s  = __ldg(&scales[f >> 12]);

            // LR: 8 bf16 = one 16B conflict-free LDS.128
            uint4 lr4 = *reinterpret_cast<const uint4*>(&Cs[r * CS_STRIDE + tx * 8]);
            float2 l0 = __bfloat1622float2(*reinterpret_cast<__nv_bfloat162*>(&lr4.x));
            float2 l1 = __bfloat1622float2(*reinterpret_cast<__nv_bfloat162*>(&lr4.y));
            float2 l2 = __bfloat1622float2(*reinterpret_cast<__nv_bfloat162*>(&lr4.z));
            float2 l3 = __bfloat1622float2(*reinterpret_cast<__nv_bfloat162*>(&lr4.w));

            float4 o0, o1;
            o0.x = fmaf(c0.x, s, l0.x);
            o0.y = fmaf(c0.y, s, l0.y);
            o0.z = fmaf(c0.z, s, l1.x);
            o0.w = fmaf(c0.w, s, l1.y);
            o1.x = fmaf(c1.x, s, l2.x);
            o1.y = fmaf(c1.y, s, l2.y);
            o1.z = fmaf(c1.z, s, l3.x);
            o1.w = fmaf(c1.w, s, l3.y);

            *reinterpret_cast<float4*>(&out[f])     = o0;
            *reinterpret_cast<float4*>(&out[f + 4]) = o1;
        }
    }
}

extern "C" void kernel_launch(void* const* d_in, const int* in_sizes, int n_in,
                              void* d_out, int out_size) {
    const float* codebooks = (const float*)d_in[0];
    const int*   codes     = (const int*)  d_in[1];
    const float* scales    = (const float*)d_in[2];
    const float* L         = (const float*)d_in[3];
    const float* R         = (const float*)d_in[4];
    float*       out       = (float*)d_out;

    cudaFuncSetAttribute(qw_hmma_kernel,
                         cudaFuncAttributeMaxDynamicSharedMemorySize, SMEM_TOTAL);

    dim3 grid(COLS / TJ, ROWS / TI);   // (86, 32)
    qw_hmma_kernel<<<grid, THREADS, SMEM_TOTAL>>>(codebooks, codes, scales, L, R, out);
}

// round 4
// speedup vs baseline: 1.4399x; 1.0358x over previous
#include <cuda_runtime.h>
#include <cuda_bf16.h>
#include <cstdint>

#define ROWS 4096
#define COLS 11008
#define RANK 32
#define GROUPS_PER_ROW 1376   // COLS/8
#define I_SPLIT 2048          // i >= 2048 -> codebook 1

#define TI 128
#define TJ 128
#define THREADS 256

// smem strides (conflict-free)
#define AS_STRIDE 40          // bf16
#define BS_STRIDE 40          // bf16
#define CBS_STRIDE 10         // floats per padded codebook entry
#define CODES_STRIDE 17       // ints

#define AS_BYTES (TI * AS_STRIDE * 2)             // 10240
#define BS_BYTES (TJ * BS_STRIDE * 2)             // 10240
#define CBS_BYTES (512 * CBS_STRIDE * 4)          // 20480
#define CODES_BYTES (TI * CODES_STRIDE * 4)       // 8704
#define SMEM_TOTAL (AS_BYTES + BS_BYTES + CBS_BYTES + CODES_BYTES)  // 49664

__global__ __launch_bounds__(THREADS, 3)
void qw_fused_kernel(const float* __restrict__ codebooks,  // (2,256,8)
                     const int*   __restrict__ codes,      // flat
                     const float* __restrict__ scales,     // (11008,)
                     const float* __restrict__ L,          // (4096,32)
                     const float* __restrict__ R,          // (32,11008)
                     float*       __restrict__ out)        // (4096,11008)
{
    extern __shared__ char smem[];
    __nv_bfloat16* As      = reinterpret_cast<__nv_bfloat16*>(smem);
    __nv_bfloat16* Bs      = reinterpret_cast<__nv_bfloat16*>(smem + AS_BYTES);
    float*         cbs     = reinterpret_cast<float*>(smem + AS_BYTES + BS_BYTES);
    int*           codes_s = reinterpret_cast<int*>(smem + AS_BYTES + BS_BYTES + CBS_BYTES);

    const int tid = threadIdx.x;
    const int wid = tid >> 5;
    const int lid = tid & 31;
    const int i0  = blockIdx.y * TI;
    const int j0  = blockIdx.x * TJ;

    // ---- stage codebooks, padded to 10 floats/entry (bank spread) ----
    #pragma unroll
    for (int e = tid; e < 512; e += THREADS) {
        const float2* src = reinterpret_cast<const float2*>(codebooks + e * 8);
        float2*       dst = reinterpret_cast<float2*>(cbs + e * CBS_STRIDE);
        dst[0] = src[0]; dst[1] = src[1]; dst[2] = src[2]; dst[3] = src[3];
    }
    // ---- stage A = L tile [128 x 32] bf16 ----
    #pragma unroll
    for (int idx = tid; idx < TI * RANK; idx += THREADS) {
        int row = idx >> 5, k = idx & 31;
        As[row * AS_STRIDE + k] = __float2bfloat16(L[(i0 + row) * RANK + k]);
    }
    // ---- stage B = R^T tile [128n x 32k] bf16 ----
    #pragma unroll
    for (int idx = tid; idx < TJ * RANK; idx += THREADS) {
        int k = idx >> 7, n = idx & 127;
        Bs[n * BS_STRIDE + k] = __float2bfloat16(R[k * COLS + j0 + n]);
    }
    // ---- stage codes tile [128 rows x 16 groups] ----
    #pragma unroll
    for (int idx = tid; idx < TI * 16; idx += THREADS) {
        int row = idx >> 4, t = idx & 15;
        codes_s[row * CODES_STRIDE + t] =
            codes[(i0 + row) * GROUPS_PER_ROW + (j0 >> 3) + t];
    }
    __syncthreads();

    // ---- fragment identity ----
    const int rfrag = lid >> 2;
    const int q     = lid & 3;
    const int r0    = wid * 16 + rfrag;   // local rows r0 and r0+8
    const int r1    = r0 + 8;

    // A fragments (k=0..31 fixed, loaded once; conflict-free)
    uint32_t a0 = *reinterpret_cast<const uint32_t*>(&As[r0 * AS_STRIDE + 2 * q]);
    uint32_t a1 = *reinterpret_cast<const uint32_t*>(&As[r1 * AS_STRIDE + 2 * q]);
    uint32_t a2 = *reinterpret_cast<const uint32_t*>(&As[r0 * AS_STRIDE + 2 * q + 8]);
    uint32_t a3 = *reinterpret_cast<const uint32_t*>(&As[r1 * AS_STRIDE + 2 * q + 8]);
    uint32_t a4 = *reinterpret_cast<const uint32_t*>(&As[r0 * AS_STRIDE + 16 + 2 * q]);
    uint32_t a5 = *reinterpret_cast<const uint32_t*>(&As[r1 * AS_STRIDE + 16 + 2 * q]);
    uint32_t a6 = *reinterpret_cast<const uint32_t*>(&As[r0 * AS_STRIDE + 24 + 2 * q]);
    uint32_t a7 = *reinterpret_cast<const uint32_t*>(&As[r1 * AS_STRIDE + 24 + 2 * q]);

    const int gi0 = i0 + r0;
    const int gi1 = i0 + r1;
    const float* cb0 = cbs + ((gi0 >= I_SPLIT) ? 256 * CBS_STRIDE : 0);
    const float* cb1 = cbs + ((gi1 >= I_SPLIT) ? 256 * CBS_STRIDE : 0);

    // per-row scale: index (i*COLS + j)>>12 increments at most once across the tile
    const unsigned base0 = (unsigned)gi0 * COLS + (unsigned)j0;
    const unsigned base1 = (unsigned)gi1 * COLS + (unsigned)j0;
    const int sidx0 = (int)(base0 >> 12);
    const int sidx1 = (int)(base1 >> 12);
    const int tB0 = (int)((4096u - (base0 & 4095u) + 7u) >> 3);  // first t using sidx+1
    const int tB1 = (int)((4096u - (base1 & 4095u) + 7u) >> 3);
    const float sLo0 = __ldg(&scales[sidx0]);
    const float sHi0 = __ldg(&scales[(sidx0 + 1 < COLS) ? sidx0 + 1 : COLS - 1]);
    const float sLo1 = __ldg(&scales[sidx1]);
    const float sHi1 = __ldg(&scales[(sidx1 + 1 < COLS) ? sidx1 + 1 : COLS - 1]);

    const int crow0 = r0 * CODES_STRIDE;
    const int crow1 = r1 * CODES_STRIDE;

    #pragma unroll
    for (int t = 0; t < 16; t++) {
        // B fragments for n-tile t (conflict-free)
        const int nb = (t * 8 + rfrag) * BS_STRIDE;
        uint32_t b0 = *reinterpret_cast<const uint32_t*>(&Bs[nb + 2 * q]);
        uint32_t b1 = *reinterpret_cast<const uint32_t*>(&Bs[nb + 2 * q + 8]);
        uint32_t b2 = *reinterpret_cast<const uint32_t*>(&Bs[nb + 16 + 2 * q]);
        uint32_t b3 = *reinterpret_cast<const uint32_t*>(&Bs[nb + 16 + 2 * q + 8]);

        float c0 = 0.f, c1 = 0.f, c2 = 0.f, c3 = 0.f;
        asm volatile(
            "mma.sync.aligned.m16n8k16.row.col.f32.bf16.bf16.f32 "
            "{%0,%1,%2,%3}, {%4,%5,%6,%7}, {%8,%9}, {%0,%1,%2,%3};"
            : "+f"(c0), "+f"(c1), "+f"(c2), "+f"(c3)
            : "r"(a0), "r"(a1), "r"(a2), "r"(a3), "r"(b0), "r"(b1));
        asm volatile(
            "mma.sync.aligned.m16n8k16.row.col.f32.bf16.bf16.f32 "
            "{%0,%1,%2,%3}, {%4,%5,%6,%7}, {%8,%9}, {%0,%1,%2,%3};"
            : "+f"(c0), "+f"(c1), "+f"(c2), "+f"(c3)
            : "r"(a4), "r"(a5), "r"(a6), "r"(a7), "r"(b2), "r"(b3));

        // fused dequant epilogue for this code group
        const int code0 = codes_s[crow0 + t];
        const int code1 = codes_s[crow1 + t];
        const float2 e0 = *reinterpret_cast<const float2*>(cb0 + code0 * CBS_STRIDE + 2 * q);
        const float2 e1 = *reinterpret_cast<const float2*>(cb1 + code1 * CBS_STRIDE + 2 * q);
        const float s0 = (t >= tB0) ? sHi0 : sLo0;
        const float s1 = (t >= tB1) ? sHi1 : sLo1;

        float2 o0, o1;
        o0.x = fmaf(e0.x, s0, c0);
        o0.y = fmaf(e0.y, s0, c1);
        o1.x = fmaf(e1.x, s1, c2);
        o1.y = fmaf(e1.y, s1, c3);

        const unsigned off = (unsigned)(t * 8 + 2 * q);
        *reinterpret_cast<float2*>(&out[base0 + off]) = o0;
        *reinterpret_cast<float2*>(&out[base1 + off]) = o1;
    }
}

extern "C" void kernel_launch(void* const* d_in, const int* in_sizes, int n_in,
                              void* d_out, int out_size) {
    const float* codebooks = (const float*)d_in[0];
    const int*   codes     = (const int*)  d_in[1];
    const float* scales    = (const float*)d_in[2];
    const float* L         = (const float*)d_in[3];
    const float* R         = (const float*)d_in[4];
    float*       out       = (float*)d_out;

    cudaFuncSetAttribute(qw_fused_kernel,
                         cudaFuncAttributeMaxDynamicSharedMemorySize, SMEM_TOTAL);

    dim3 grid(COLS / TJ, ROWS / TI);   // (86, 32)
    qw_fused_kernel<<<grid, THREADS, SMEM_TOTAL>>>(codebooks, codes, scales, L, R, out);
}